// round 6
// baseline (speedup 1.0000x reference)
#include <cuda_runtime.h>
#include <cuda_fp16.h>
#include <cstdint>

// ---------------------------------------------------------------------------
// GraphConvolutionLayer: out = segment_sum(vals[e] * (x@W)[src[e]] -> dst[e]) + bias
// R6: de-fused. 3 launches:
//   1. gemm (tf32 tensor) + counter zeroing (runs first, kernel-boundary ordered)
//   2. fill: 4 edges/thread (MLP=4 on atomic->store chain), CAP=32 bucket (L2-resident)
//   3. gather: per-dst warp accumulate + in-kernel overflow scan, one store/node
// ---------------------------------------------------------------------------

#define IN_F  128
#define OUT_F 64
#define MAX_NODES 100000
#define CAP 32
#define OVF_CAP 65536

__device__ __half g_support[(size_t)MAX_NODES * OUT_F];
__device__ int    g_count[MAX_NODES];
__device__ int2   g_bucket[(size_t)MAX_NODES * CAP];   // 25.6 MB
__device__ int    g_ovf_count;
__device__ int4   g_ovf[OVF_CAP];

#define BM 128
#define BK 32

__device__ __forceinline__ uint32_t f2tf32(float v) {
    uint32_t t;
    asm("cvt.rna.tf32.f32 %0, %1;" : "=r"(t) : "f"(v));
    return t;
}

// ---------------------------------------------------------------------------
// Kernel 1: tf32 tensor GEMM (+ zero counters for the later kernels)
// ---------------------------------------------------------------------------
__global__ __launch_bounds__(256)
void gemm_kernel(const float* __restrict__ A,   // [M,128]
                 const float* __restrict__ W,   // [128,64]
                 __half*      __restrict__ C,   // [M,64] fp16
                 int M) {
    // zero g_count / g_ovf_count (ordered before fill by kernel boundary)
    {
        int t = blockIdx.x * blockDim.x + threadIdx.x;
        if (t < M) g_count[t] = 0;
        if (t == M) g_ovf_count = 0;
    }

    __shared__ uint32_t As[8 * 4 * 32 * 4];   // 16 KB, fragment-major
    __shared__ uint32_t Bs[8 * 4 * 32 * 2];   //  8 KB

    int tid  = threadIdx.x;
    int lane = tid & 31;
    int wid  = tid >> 5;
    int wm   = wid >> 1;          // 0..3
    int wn   = wid & 1;           // 0..1
    int rowBase = blockIdx.x * BM;

    float acc[2][4][4];
    #pragma unroll
    for (int i = 0; i < 2; i++)
        #pragma unroll
        for (int j = 0; j < 4; j++)
            #pragma unroll
            for (int q = 0; q < 4; q++) acc[i][j][q] = 0.f;

    for (int kBase = 0; kBase < IN_F; kBase += BK) {
        #pragma unroll
        for (int it = 0; it < 4; it++) {
            int idx = tid + it * 256;
            int row = idx >> 3;
            int c4  = idx & 7;
            int grow = rowBase + row;
            float4 v = make_float4(0.f, 0.f, 0.f, 0.f);
            if (grow < M)
                v = *reinterpret_cast<const float4*>(A + (size_t)grow * IN_F + kBase + c4 * 4);
            int g   = row >> 4;
            int rr  = row & 15;
            int sel = rr >> 3;
            int lr  = rr & 7;
            int kb  = c4 >> 1;
            int hi  = c4 & 1;
            int base = (((g * 4 + kb) * 32 + lr * 4) << 2) + hi * 2 + sel;
            As[base +  0] = f2tf32(v.x);
            As[base +  4] = f2tf32(v.y);
            As[base +  8] = f2tf32(v.z);
            As[base + 12] = f2tf32(v.w);
        }
        #pragma unroll
        for (int it = 0; it < 2; it++) {
            int idx  = tid + it * 256;
            int krow = idx >> 4;
            int n4   = idx & 15;
            float4 v = *reinterpret_cast<const float4*>(W + (size_t)(kBase + krow) * OUT_F + n4 * 4);
            int kb = krow >> 3;
            int w8 = krow & 7;
            int lc = w8 & 3;
            int hi = w8 >> 2;
            int nb = n4 >> 1;
            int lgb = (n4 & 1) * 4;
            int base = (((nb * 4 + kb) * 32 + lgb * 4 + lc) << 1) + hi;
            Bs[base +  0] = f2tf32(v.x);
            Bs[base +  8] = f2tf32(v.y);
            Bs[base + 16] = f2tf32(v.z);
            Bs[base + 24] = f2tf32(v.w);
        }
        __syncthreads();

        #pragma unroll
        for (int kb = 0; kb < 4; kb++) {
            uint4 fa[2];
            uint2 fb[4];
            #pragma unroll
            for (int i = 0; i < 2; i++)
                fa[i] = *reinterpret_cast<const uint4*>(
                    &As[(((2 * wm + i) * 4 + kb) * 32 + lane) << 2]);
            #pragma unroll
            for (int j = 0; j < 4; j++)
                fb[j] = *reinterpret_cast<const uint2*>(
                    &Bs[(((wn * 4 + j) * 4 + kb) * 32 + lane) << 1]);
            #pragma unroll
            for (int i = 0; i < 2; i++)
                #pragma unroll
                for (int j = 0; j < 4; j++) {
                    asm volatile(
                        "mma.sync.aligned.m16n8k8.row.col.f32.tf32.tf32.f32 "
                        "{%0,%1,%2,%3}, {%4,%5,%6,%7}, {%8,%9}, {%0,%1,%2,%3};"
                        : "+f"(acc[i][j][0]), "+f"(acc[i][j][1]),
                          "+f"(acc[i][j][2]), "+f"(acc[i][j][3])
                        : "r"(fa[i].x), "r"(fa[i].y), "r"(fa[i].z), "r"(fa[i].w),
                          "r"(fb[j].x), "r"(fb[j].y));
                }
        }
        __syncthreads();
    }

    #pragma unroll
    for (int i = 0; i < 2; i++) {
        int r0 = rowBase + wm * 32 + i * 16 + (lane >> 2);
        int r1 = r0 + 8;
        #pragma unroll
        for (int j = 0; j < 4; j++) {
            int cbase = wn * 32 + j * 8 + (lane & 3) * 2;
            if (r0 < M) {
                __half2 h = __float22half2_rn(make_float2(acc[i][j][0], acc[i][j][1]));
                *reinterpret_cast<uint32_t*>(C + (size_t)r0 * OUT_F + cbase) = *(uint32_t*)&h;
            }
            if (r1 < M) {
                __half2 h = __float22half2_rn(make_float2(acc[i][j][2], acc[i][j][3]));
                *reinterpret_cast<uint32_t*>(C + (size_t)r1 * OUT_F + cbase) = *(uint32_t*)&h;
            }
        }
    }
}

// ---------------------------------------------------------------------------
// Kernel 2: fill — 4 edges per thread, vectorized loads, MLP=4 atomic chains
// ---------------------------------------------------------------------------
__global__ __launch_bounds__(256)
void fill_kernel(const int*   __restrict__ src,
                 const int*   __restrict__ dst,
                 const float* __restrict__ vals,
                 int nE) {
    int t  = blockIdx.x * blockDim.x + threadIdx.x;
    int e0 = t * 4;
    if (e0 >= nE) return;

    if (e0 + 4 <= nE) {
        int4   s4 = *reinterpret_cast<const int4*>(src + e0);
        int4   d4 = *reinterpret_cast<const int4*>(dst + e0);
        float4 v4 = *reinterpret_cast<const float4*>(vals + e0);
        int ss[4] = {s4.x, s4.y, s4.z, s4.w};
        int dd[4] = {d4.x, d4.y, d4.z, d4.w};
        float vv[4] = {v4.x, v4.y, v4.z, v4.w};
        int pos[4];
        #pragma unroll
        for (int i = 0; i < 4; i++)
            pos[i] = atomicAdd(&g_count[dd[i]], 1);     // 4 independent chains
        #pragma unroll
        for (int i = 0; i < 4; i++) {
            if (pos[i] < CAP) {
                g_bucket[(size_t)dd[i] * CAP + pos[i]] = make_int2(ss[i], __float_as_int(vv[i]));
            } else {
                int o = atomicAdd(&g_ovf_count, 1);
                if (o < OVF_CAP) g_ovf[o] = make_int4(ss[i], dd[i], __float_as_int(vv[i]), 0);
            }
        }
    } else {
        for (int e = e0; e < nE; e++) {
            int   s = __ldg(&src[e]);
            int   d = __ldg(&dst[e]);
            float v = __ldg(&vals[e]);
            int pos = atomicAdd(&g_count[d], 1);
            if (pos < CAP) {
                g_bucket[(size_t)d * CAP + pos] = make_int2(s, __float_as_int(v));
            } else {
                int o = atomicAdd(&g_ovf_count, 1);
                if (o < OVF_CAP) g_ovf[o] = make_int4(s, d, __float_as_int(v), 0);
            }
        }
    }
}

// ---------------------------------------------------------------------------
// Kernel 3: gather — one warp per dst node + in-kernel overflow scan
// ---------------------------------------------------------------------------
__global__ __launch_bounds__(256)
void gather_kernel(const __half* __restrict__ support,
                   const float*  __restrict__ bias,
                   float* __restrict__ out, int M) {
    int w    = (blockIdx.x * blockDim.x + threadIdx.x) >> 5;
    int lane = threadIdx.x & 31;
    if (w >= M) return;

    int deg = g_count[w];
    int nb  = deg < CAP ? deg : CAP;

    float2 acc = make_float2(0.f, 0.f);
    const int2* bkt = g_bucket + (size_t)w * CAP;

    #pragma unroll 4
    for (int j = 0; j < nb; j++) {
        int2 pr = __ldg(&bkt[j]);                          // warp-broadcast
        float v = __int_as_float(pr.y);
        const uint32_t* row = reinterpret_cast<const uint32_t*>(
            support + (size_t)pr.x * OUT_F);
        uint32_t h2raw = __ldg(&row[lane]);
        float2 f = __half22float2(*reinterpret_cast<__half2*>(&h2raw));
        acc.x += v * f.x;
        acc.y += v * f.y;
    }

    // overflow scan (only warps whose node exceeded CAP; list is ~tens)
    if (deg > CAP) {
        int n = g_ovf_count;
        if (n > OVF_CAP) n = OVF_CAP;
        for (int i = 0; i < n; i++) {
            int4 r = g_ovf[i];                             // broadcast
            if (r.y == w) {
                float v = __int_as_float(r.z);
                const uint32_t* row = reinterpret_cast<const uint32_t*>(
                    support + (size_t)r.x * OUT_F);
                uint32_t h2raw = __ldg(&row[lane]);
                float2 f = __half22float2(*reinterpret_cast<__half2*>(&h2raw));
                acc.x += v * f.x;
                acc.y += v * f.y;
            }
        }
    }

    float2 b = __ldg(reinterpret_cast<const float2*>(bias) + lane);
    float2 r = make_float2(acc.x + b.x, acc.y + b.y);
    *reinterpret_cast<float2*>(out + (size_t)w * OUT_F + 2 * lane) = r;
}

// ---------------------------------------------------------------------------
extern "C" void kernel_launch(void* const* d_in, const int* in_sizes, int n_in,
                              void* d_out, int out_size) {
    const float* x        = (const float*)d_in[0];
    const float* weight   = (const float*)d_in[1];
    const float* bias     = (const float*)d_in[2];
    const int*   edge_src = (const int*)  d_in[3];
    const int*   edge_dst = (const int*)  d_in[4];
    const float* edge_val = (const float*)d_in[5];
    float* out = (float*)d_out;

    int M  = in_sizes[0] / IN_F;
    int nE = in_sizes[3];

    __half* support; cudaGetSymbolAddress((void**)&support, g_support);

    // 1) GEMM (also zeroes counters for fill/gather)
    gemm_kernel<<<(M + BM - 1) / BM, 256>>>(x, weight, support, M);

    // 2) bucket edges by dst, 4 edges/thread
    {
        int threadsNeeded = (nE + 3) / 4;
        fill_kernel<<<(threadsNeeded + 255) / 256, 256>>>(edge_src, edge_dst, edge_val, nE);
    }

    // 3) per-node gather (+bias, +overflow), one store per node
    gather_kernel<<<(M * 32 + 255) / 256, 256>>>(support, bias, out, M);
}

// round 8
// speedup vs baseline: 1.0032x; 1.0032x over previous
#include <cuda_runtime.h>
#include <cuda_fp16.h>
#include <cstdint>

// ---------------------------------------------------------------------------
// GraphConvolutionLayer: out = segment_sum(vals[e] * (x@W)[src[e]] -> dst[e]) + bias
// R7 resubmit (infra ate the previous run):
//   pipelined conflict-free tf32 GEMM (row-major padded smem, register
//   double-buffer), fill with 8 edges/thread, gather with 2 nodes/warp.
// ---------------------------------------------------------------------------

#define IN_F  128
#define OUT_F 64
#define MAX_NODES 100000
#define CAP 32
#define OVF_CAP 65536

__device__ __half g_support[(size_t)MAX_NODES * OUT_F];
__device__ int    g_count[MAX_NODES];
__device__ int2   g_bucket[(size_t)MAX_NODES * CAP];
__device__ int    g_ovf_count;
__device__ int4   g_ovf[OVF_CAP];

#define BM 128
#define BK 32
#define A_STRIDE 36   // 32 + 4 pad words -> bank-conflict-free frag loads
#define W_STRIDE 68   // 64 + 4 pad words

__device__ __forceinline__ uint32_t f2tf32(float v) {
    uint32_t t;
    asm("cvt.rna.tf32.f32 %0, %1;" : "=r"(t) : "f"(v));
    return t;
}

// ---------------------------------------------------------------------------
// Kernel 1: pipelined tf32 GEMM (+ zero counters for later kernels)
// ---------------------------------------------------------------------------
__global__ __launch_bounds__(256)
void gemm_kernel(const float* __restrict__ A,   // [M,128]
                 const float* __restrict__ W,   // [128,64]
                 __half*      __restrict__ C,   // [M,64] fp16
                 int M) {
    // zero bucket counters (kernel-boundary ordered before fill)
    {
        int t = blockIdx.x * blockDim.x + threadIdx.x;
        if (t < M) g_count[t] = 0;
        if (t == 0) g_ovf_count = 0;
    }

    __shared__ uint32_t As[BM * A_STRIDE];   // 18.4 KB
    __shared__ uint32_t Ws[BK * W_STRIDE];   //  8.7 KB

    int tid  = threadIdx.x;
    int lane = tid & 31;
    int wid  = tid >> 5;
    int wm   = wid >> 1;        // 0..3
    int wn   = wid & 1;         // 0..1
    int rowBase = blockIdx.x * BM;

    // A-staging coords: idx = tid + it*256 -> row = tid>>3 + 32*it, c4 = tid&7
    int arow = tid >> 3, ac4 = tid & 7;
    // W-staging coords: idx = tid + it*256 -> krow = tid>>4 + 16*it, n4 = tid&15
    int wrow = tid >> 4, wn4 = tid & 15;

    float4 pa[4];
    float4 pw[2];

    // prefetch stage 0
    #pragma unroll
    for (int it = 0; it < 4; it++) {
        int grow = rowBase + arow + it * 32;
        pa[it] = (grow < M)
            ? *reinterpret_cast<const float4*>(A + (size_t)grow * IN_F + ac4 * 4)
            : make_float4(0.f, 0.f, 0.f, 0.f);
    }
    #pragma unroll
    for (int it = 0; it < 2; it++)
        pw[it] = *reinterpret_cast<const float4*>(W + (size_t)(wrow + it * 16) * OUT_F + wn4 * 4);

    float acc[2][4][4];
    #pragma unroll
    for (int i = 0; i < 2; i++)
        #pragma unroll
        for (int j = 0; j < 4; j++)
            #pragma unroll
            for (int q = 0; q < 4; q++) acc[i][j][q] = 0.f;

    int r = lane >> 2, c = lane & 3;

    #pragma unroll
    for (int s = 0; s < 4; s++) {
        // stage current (STS.128, conflict-free quarter-warps)
        #pragma unroll
        for (int it = 0; it < 4; it++) {
            uint4 u = make_uint4(f2tf32(pa[it].x), f2tf32(pa[it].y),
                                 f2tf32(pa[it].z), f2tf32(pa[it].w));
            *reinterpret_cast<uint4*>(&As[(arow + it * 32) * A_STRIDE + ac4 * 4]) = u;
        }
        #pragma unroll
        for (int it = 0; it < 2; it++) {
            uint4 u = make_uint4(f2tf32(pw[it].x), f2tf32(pw[it].y),
                                 f2tf32(pw[it].z), f2tf32(pw[it].w));
            *reinterpret_cast<uint4*>(&Ws[(wrow + it * 16) * W_STRIDE + wn4 * 4]) = u;
        }
        __syncthreads();

        // prefetch next stage (LDG latency hides under compute below)
        if (s < 3) {
            int kOff = (s + 1) * BK;
            #pragma unroll
            for (int it = 0; it < 4; it++) {
                int grow = rowBase + arow + it * 32;
                pa[it] = (grow < M)
                    ? *reinterpret_cast<const float4*>(A + (size_t)grow * IN_F + kOff + ac4 * 4)
                    : make_float4(0.f, 0.f, 0.f, 0.f);
            }
            #pragma unroll
            for (int it = 0; it < 2; it++)
                pw[it] = *reinterpret_cast<const float4*>(
                    W + (size_t)(kOff + wrow + it * 16) * OUT_F + wn4 * 4);
        }

        // compute: 4 k-blocks of 8
        #pragma unroll
        for (int kb = 0; kb < 4; kb++) {
            uint32_t fa[2][4];
            #pragma unroll
            for (int i = 0; i < 2; i++) {
                int m0 = (wm * 32 + i * 16 + r) * A_STRIDE + kb * 8 + c;
                fa[i][0] = As[m0];
                fa[i][1] = As[m0 + 8 * A_STRIDE];
                fa[i][2] = As[m0 + 4];
                fa[i][3] = As[m0 + 8 * A_STRIDE + 4];
            }
            uint32_t fb[4][2];
            #pragma unroll
            for (int j = 0; j < 4; j++) {
                int b0 = (kb * 8 + c) * W_STRIDE + wn * 32 + j * 8 + r;
                fb[j][0] = Ws[b0];
                fb[j][1] = Ws[b0 + 4 * W_STRIDE];
            }
            #pragma unroll
            for (int i = 0; i < 2; i++)
                #pragma unroll
                for (int j = 0; j < 4; j++) {
                    asm volatile(
                        "mma.sync.aligned.m16n8k8.row.col.f32.tf32.tf32.f32 "
                        "{%0,%1,%2,%3}, {%4,%5,%6,%7}, {%8,%9}, {%0,%1,%2,%3};"
                        : "+f"(acc[i][j][0]), "+f"(acc[i][j][1]),
                          "+f"(acc[i][j][2]), "+f"(acc[i][j][3])
                        : "r"(fa[i][0]), "r"(fa[i][1]), "r"(fa[i][2]), "r"(fa[i][3]),
                          "r"(fb[j][0]), "r"(fb[j][1]));
                }
        }
        __syncthreads();
    }

    // epilogue: fp16 store (layout identical to validated R5 path)
    #pragma unroll
    for (int i = 0; i < 2; i++) {
        int r0 = rowBase + wm * 32 + i * 16 + r;
        int r1 = r0 + 8;
        #pragma unroll
        for (int j = 0; j < 4; j++) {
            int cbase = wn * 32 + j * 8 + c * 2;
            if (r0 < M) {
                __half2 h = __float22half2_rn(make_float2(acc[i][j][0], acc[i][j][1]));
                *reinterpret_cast<uint32_t*>(C + (size_t)r0 * OUT_F + cbase) = *(uint32_t*)&h;
            }
            if (r1 < M) {
                __half2 h = __float22half2_rn(make_float2(acc[i][j][2], acc[i][j][3]));
                *reinterpret_cast<uint32_t*>(C + (size_t)r1 * OUT_F + cbase) = *(uint32_t*)&h;
            }
        }
    }
}

// ---------------------------------------------------------------------------
// Kernel 2: fill — 8 edges per thread (MLP=8 atomic->store chains)
// ---------------------------------------------------------------------------
__global__ __launch_bounds__(256)
void fill_kernel(const int*   __restrict__ src,
                 const int*   __restrict__ dst,
                 const float* __restrict__ vals,
                 int nE) {
    int t  = blockIdx.x * blockDim.x + threadIdx.x;
    int e0 = t * 8;
    if (e0 >= nE) return;

    if (e0 + 8 <= nE) {
        int4 sa = *reinterpret_cast<const int4*>(src + e0);
        int4 sb = *reinterpret_cast<const int4*>(src + e0 + 4);
        int4 da = *reinterpret_cast<const int4*>(dst + e0);
        int4 db = *reinterpret_cast<const int4*>(dst + e0 + 4);
        float4 va = *reinterpret_cast<const float4*>(vals + e0);
        float4 vb = *reinterpret_cast<const float4*>(vals + e0 + 4);
        int ss[8] = {sa.x, sa.y, sa.z, sa.w, sb.x, sb.y, sb.z, sb.w};
        int dd[8] = {da.x, da.y, da.z, da.w, db.x, db.y, db.z, db.w};
        float vv[8] = {va.x, va.y, va.z, va.w, vb.x, vb.y, vb.z, vb.w};
        int pos[8];
        #pragma unroll
        for (int i = 0; i < 8; i++)
            pos[i] = atomicAdd(&g_count[dd[i]], 1);     // 8 independent chains
        #pragma unroll
        for (int i = 0; i < 8; i++) {
            if (pos[i] < CAP) {
                g_bucket[(size_t)dd[i] * CAP + pos[i]] = make_int2(ss[i], __float_as_int(vv[i]));
            } else {
                int o = atomicAdd(&g_ovf_count, 1);
                if (o < OVF_CAP) g_ovf[o] = make_int4(ss[i], dd[i], __float_as_int(vv[i]), 0);
            }
        }
    } else {
        for (int e = e0; e < nE; e++) {
            int   s = __ldg(&src[e]);
            int   d = __ldg(&dst[e]);
            float v = __ldg(&vals[e]);
            int pos = atomicAdd(&g_count[d], 1);
            if (pos < CAP) {
                g_bucket[(size_t)d * CAP + pos] = make_int2(s, __float_as_int(v));
            } else {
                int o = atomicAdd(&g_ovf_count, 1);
                if (o < OVF_CAP) g_ovf[o] = make_int4(s, d, __float_as_int(v), 0);
            }
        }
    }
}

// ---------------------------------------------------------------------------
// Kernel 3: gather — 2 dst nodes per warp (2 independent chains), one store
//           per node; in-kernel overflow scan backstop
// ---------------------------------------------------------------------------
__global__ __launch_bounds__(256)
void gather_kernel(const __half* __restrict__ support,
                   const float*  __restrict__ bias,
                   float* __restrict__ out, int M) {
    int q    = (blockIdx.x * blockDim.x + threadIdx.x) >> 5;
    int lane = threadIdx.x & 31;
    int n0 = q * 2, n1 = q * 2 + 1;
    if (n0 >= M) return;
    bool has1 = (n1 < M);

    int deg0 = g_count[n0];
    int deg1 = has1 ? g_count[n1] : 0;
    int nb0 = deg0 < CAP ? deg0 : CAP;
    int nb1 = deg1 < CAP ? deg1 : CAP;

    const int2* b0 = g_bucket + (size_t)n0 * CAP;
    const int2* b1 = g_bucket + (size_t)n1 * CAP;

    float2 a0 = make_float2(0.f, 0.f);
    float2 a1 = make_float2(0.f, 0.f);

    int jm = nb0 > nb1 ? nb0 : nb1;
    #pragma unroll 2
    for (int j = 0; j < jm; j++) {
        if (j < nb0) {
            int2 pr = __ldg(&b0[j]);
            float v = __int_as_float(pr.y);
            uint32_t h2 = __ldg(reinterpret_cast<const uint32_t*>(
                support + (size_t)pr.x * OUT_F) + lane);
            float2 f = __half22float2(*reinterpret_cast<__half2*>(&h2));
            a0.x += v * f.x;
            a0.y += v * f.y;
        }
        if (j < nb1) {
            int2 pr = __ldg(&b1[j]);
            float v = __int_as_float(pr.y);
            uint32_t h2 = __ldg(reinterpret_cast<const uint32_t*>(
                support + (size_t)pr.x * OUT_F) + lane);
            float2 f = __half22float2(*reinterpret_cast<__half2*>(&h2));
            a1.x += v * f.x;
            a1.y += v * f.y;
        }
    }

    // overflow backstop (list is ~tens of entries in the worst case)
    if (deg0 > CAP || deg1 > CAP) {
        int n = g_ovf_count;
        if (n > OVF_CAP) n = OVF_CAP;
        for (int i = 0; i < n; i++) {
            int4 rr = g_ovf[i];
            if (rr.y == n0 || rr.y == n1) {
                float v = __int_as_float(rr.z);
                uint32_t h2 = __ldg(reinterpret_cast<const uint32_t*>(
                    support + (size_t)rr.x * OUT_F) + lane);
                float2 f = __half22float2(*reinterpret_cast<__half2*>(&h2));
                if (rr.y == n0) { a0.x += v * f.x; a0.y += v * f.y; }
                else            { a1.x += v * f.x; a1.y += v * f.y; }
            }
        }
    }

    float2 b = __ldg(reinterpret_cast<const float2*>(bias) + lane);
    *reinterpret_cast<float2*>(out + (size_t)n0 * OUT_F + 2 * lane) =
        make_float2(a0.x + b.x, a0.y + b.y);
    if (has1)
        *reinterpret_cast<float2*>(out + (size_t)n1 * OUT_F + 2 * lane) =
            make_float2(a1.x + b.x, a1.y + b.y);
}

// ---------------------------------------------------------------------------
extern "C" void kernel_launch(void* const* d_in, const int* in_sizes, int n_in,
                              void* d_out, int out_size) {
    const float* x        = (const float*)d_in[0];
    const float* weight   = (const float*)d_in[1];
    const float* bias     = (const float*)d_in[2];
    const int*   edge_src = (const int*)  d_in[3];
    const int*   edge_dst = (const int*)  d_in[4];
    const float* edge_val = (const float*)d_in[5];
    float* out = (float*)d_out;

    int M  = in_sizes[0] / IN_F;
    int nE = in_sizes[3];

    __half* support; cudaGetSymbolAddress((void**)&support, g_support);

    // 1) GEMM (also zeroes counters for fill/gather)
    gemm_kernel<<<(M + BM - 1) / BM, 256>>>(x, weight, support, M);

    // 2) bucket edges by dst, 8 edges/thread
    {
        int threadsNeeded = (nE + 7) / 8;
        fill_kernel<<<(threadsNeeded + 255) / 256, 256>>>(edge_src, edge_dst, edge_val, nE);
    }

    // 3) gather: 2 nodes/warp (+bias, +overflow)
    {
        int warps = (M + 1) / 2;
        gather_kernel<<<(warps * 32 + 255) / 256, 256>>>(support, bias, out, M);
    }
}

// round 9
// speedup vs baseline: 1.2312x; 1.2273x over previous
#include <cuda_runtime.h>
#include <cuda_fp16.h>
#include <cstdint>

// ---------------------------------------------------------------------------
// GraphConvolutionLayer: out = segment_sum(vals[e] * (x@W)[src[e]] -> dst[e]) + bias
// R9: best-of-measured combination:
//   - R8 pipelined conflict-free tf32 GEMM (26.3us measured)
//   - R6 fill (4 edges/thread)  + R6 gather (1 node/warp)  (measured faster
//     than the R7/R8 wide variants by ~20us combined)
// ---------------------------------------------------------------------------

#define IN_F  128
#define OUT_F 64
#define MAX_NODES 100000
#define CAP 32
#define OVF_CAP 65536

__device__ __half g_support[(size_t)MAX_NODES * OUT_F];
__device__ int    g_count[MAX_NODES];
__device__ int2   g_bucket[(size_t)MAX_NODES * CAP];
__device__ int    g_ovf_count;
__device__ int4   g_ovf[OVF_CAP];

#define BM 128
#define BK 32
#define A_STRIDE 36   // 32 + 4 pad words -> bank-conflict-free frag loads
#define W_STRIDE 68   // 64 + 4 pad words

__device__ __forceinline__ uint32_t f2tf32(float v) {
    uint32_t t;
    asm("cvt.rna.tf32.f32 %0, %1;" : "=r"(t) : "f"(v));
    return t;
}

// ---------------------------------------------------------------------------
// Kernel 1: pipelined tf32 GEMM (+ zero counters for later kernels)
// ---------------------------------------------------------------------------
__global__ __launch_bounds__(256)
void gemm_kernel(const float* __restrict__ A,   // [M,128]
                 const float* __restrict__ W,   // [128,64]
                 __half*      __restrict__ C,   // [M,64] fp16
                 int M) {
    // zero bucket counters (kernel-boundary ordered before fill)
    {
        int t = blockIdx.x * blockDim.x + threadIdx.x;
        if (t < M) g_count[t] = 0;
        if (t == 0) g_ovf_count = 0;
    }

    __shared__ uint32_t As[BM * A_STRIDE];   // 18.4 KB
    __shared__ uint32_t Ws[BK * W_STRIDE];   //  8.7 KB

    int tid  = threadIdx.x;
    int lane = tid & 31;
    int wid  = tid >> 5;
    int wm   = wid >> 1;        // 0..3
    int wn   = wid & 1;         // 0..1
    int rowBase = blockIdx.x * BM;

    int arow = tid >> 3, ac4 = tid & 7;
    int wrow = tid >> 4, wn4 = tid & 15;

    float4 pa[4];
    float4 pw[2];

    // prefetch stage 0
    #pragma unroll
    for (int it = 0; it < 4; it++) {
        int grow = rowBase + arow + it * 32;
        pa[it] = (grow < M)
            ? *reinterpret_cast<const float4*>(A + (size_t)grow * IN_F + ac4 * 4)
            : make_float4(0.f, 0.f, 0.f, 0.f);
    }
    #pragma unroll
    for (int it = 0; it < 2; it++)
        pw[it] = *reinterpret_cast<const float4*>(W + (size_t)(wrow + it * 16) * OUT_F + wn4 * 4);

    float acc[2][4][4];
    #pragma unroll
    for (int i = 0; i < 2; i++)
        #pragma unroll
        for (int j = 0; j < 4; j++)
            #pragma unroll
            for (int q = 0; q < 4; q++) acc[i][j][q] = 0.f;

    int r = lane >> 2, c = lane & 3;

    #pragma unroll
    for (int s = 0; s < 4; s++) {
        #pragma unroll
        for (int it = 0; it < 4; it++) {
            uint4 u = make_uint4(f2tf32(pa[it].x), f2tf32(pa[it].y),
                                 f2tf32(pa[it].z), f2tf32(pa[it].w));
            *reinterpret_cast<uint4*>(&As[(arow + it * 32) * A_STRIDE + ac4 * 4]) = u;
        }
        #pragma unroll
        for (int it = 0; it < 2; it++) {
            uint4 u = make_uint4(f2tf32(pw[it].x), f2tf32(pw[it].y),
                                 f2tf32(pw[it].z), f2tf32(pw[it].w));
            *reinterpret_cast<uint4*>(&Ws[(wrow + it * 16) * W_STRIDE + wn4 * 4]) = u;
        }
        __syncthreads();

        if (s < 3) {
            int kOff = (s + 1) * BK;
            #pragma unroll
            for (int it = 0; it < 4; it++) {
                int grow = rowBase + arow + it * 32;
                pa[it] = (grow < M)
                    ? *reinterpret_cast<const float4*>(A + (size_t)grow * IN_F + kOff + ac4 * 4)
                    : make_float4(0.f, 0.f, 0.f, 0.f);
            }
            #pragma unroll
            for (int it = 0; it < 2; it++)
                pw[it] = *reinterpret_cast<const float4*>(
                    W + (size_t)(kOff + wrow + it * 16) * OUT_F + wn4 * 4);
        }

        #pragma unroll
        for (int kb = 0; kb < 4; kb++) {
            uint32_t fa[2][4];
            #pragma unroll
            for (int i = 0; i < 2; i++) {
                int m0 = (wm * 32 + i * 16 + r) * A_STRIDE + kb * 8 + c;
                fa[i][0] = As[m0];
                fa[i][1] = As[m0 + 8 * A_STRIDE];
                fa[i][2] = As[m0 + 4];
                fa[i][3] = As[m0 + 8 * A_STRIDE + 4];
            }
            uint32_t fb[4][2];
            #pragma unroll
            for (int j = 0; j < 4; j++) {
                int b0 = (kb * 8 + c) * W_STRIDE + wn * 32 + j * 8 + r;
                fb[j][0] = Ws[b0];
                fb[j][1] = Ws[b0 + 4 * W_STRIDE];
            }
            #pragma unroll
            for (int i = 0; i < 2; i++)
                #pragma unroll
                for (int j = 0; j < 4; j++) {
                    asm volatile(
                        "mma.sync.aligned.m16n8k8.row.col.f32.tf32.tf32.f32 "
                        "{%0,%1,%2,%3}, {%4,%5,%6,%7}, {%8,%9}, {%0,%1,%2,%3};"
                        : "+f"(acc[i][j][0]), "+f"(acc[i][j][1]),
                          "+f"(acc[i][j][2]), "+f"(acc[i][j][3])
                        : "r"(fa[i][0]), "r"(fa[i][1]), "r"(fa[i][2]), "r"(fa[i][3]),
                          "r"(fb[j][0]), "r"(fb[j][1]));
                }
        }
        __syncthreads();
    }

    #pragma unroll
    for (int i = 0; i < 2; i++) {
        int r0 = rowBase + wm * 32 + i * 16 + r;
        int r1 = r0 + 8;
        #pragma unroll
        for (int j = 0; j < 4; j++) {
            int cbase = wn * 32 + j * 8 + c * 2;
            if (r0 < M) {
                __half2 h = __float22half2_rn(make_float2(acc[i][j][0], acc[i][j][1]));
                *reinterpret_cast<uint32_t*>(C + (size_t)r0 * OUT_F + cbase) = *(uint32_t*)&h;
            }
            if (r1 < M) {
                __half2 h = __float22half2_rn(make_float2(acc[i][j][2], acc[i][j][3]));
                *reinterpret_cast<uint32_t*>(C + (size_t)r1 * OUT_F + cbase) = *(uint32_t*)&h;
            }
        }
    }
}

// ---------------------------------------------------------------------------
// Kernel 2: fill — 4 edges per thread (R6 measured-best shape)
// ---------------------------------------------------------------------------
__global__ __launch_bounds__(256)
void fill_kernel(const int*   __restrict__ src,
                 const int*   __restrict__ dst,
                 const float* __restrict__ vals,
                 int nE) {
    int t  = blockIdx.x * blockDim.x + threadIdx.x;
    int e0 = t * 4;
    if (e0 >= nE) return;

    if (e0 + 4 <= nE) {
        int4   s4 = *reinterpret_cast<const int4*>(src + e0);
        int4   d4 = *reinterpret_cast<const int4*>(dst + e0);
        float4 v4 = *reinterpret_cast<const float4*>(vals + e0);
        int ss[4] = {s4.x, s4.y, s4.z, s4.w};
        int dd[4] = {d4.x, d4.y, d4.z, d4.w};
        float vv[4] = {v4.x, v4.y, v4.z, v4.w};
        int pos[4];
        #pragma unroll
        for (int i = 0; i < 4; i++)
            pos[i] = atomicAdd(&g_count[dd[i]], 1);
        #pragma unroll
        for (int i = 0; i < 4; i++) {
            if (pos[i] < CAP) {
                g_bucket[(size_t)dd[i] * CAP + pos[i]] = make_int2(ss[i], __float_as_int(vv[i]));
            } else {
                int o = atomicAdd(&g_ovf_count, 1);
                if (o < OVF_CAP) g_ovf[o] = make_int4(ss[i], dd[i], __float_as_int(vv[i]), 0);
            }
        }
    } else {
        for (int e = e0; e < nE; e++) {
            int   s = __ldg(&src[e]);
            int   d = __ldg(&dst[e]);
            float v = __ldg(&vals[e]);
            int pos = atomicAdd(&g_count[d], 1);
            if (pos < CAP) {
                g_bucket[(size_t)d * CAP + pos] = make_int2(s, __float_as_int(v));
            } else {
                int o = atomicAdd(&g_ovf_count, 1);
                if (o < OVF_CAP) g_ovf[o] = make_int4(s, d, __float_as_int(v), 0);
            }
        }
    }
}

// ---------------------------------------------------------------------------
// Kernel 3: gather — one warp per dst node (R6 measured-best shape)
// ---------------------------------------------------------------------------
__global__ __launch_bounds__(256)
void gather_kernel(const __half* __restrict__ support,
                   const float*  __restrict__ bias,
                   float* __restrict__ out, int M) {
    int w    = (blockIdx.x * blockDim.x + threadIdx.x) >> 5;
    int lane = threadIdx.x & 31;
    if (w >= M) return;

    int deg = g_count[w];
    int nb  = deg < CAP ? deg : CAP;

    float2 acc = make_float2(0.f, 0.f);
    const int2* bkt = g_bucket + (size_t)w * CAP;

    #pragma unroll 4
    for (int j = 0; j < nb; j++) {
        int2 pr = __ldg(&bkt[j]);                          // warp-broadcast
        float v = __int_as_float(pr.y);
        const uint32_t* row = reinterpret_cast<const uint32_t*>(
            support + (size_t)pr.x * OUT_F);
        uint32_t h2raw = __ldg(&row[lane]);
        float2 f = __half22float2(*reinterpret_cast<__half2*>(&h2raw));
        acc.x += v * f.x;
        acc.y += v * f.y;
    }

    // overflow scan (only warps whose node exceeded CAP; list is ~tens)
    if (deg > CAP) {
        int n = g_ovf_count;
        if (n > OVF_CAP) n = OVF_CAP;
        for (int i = 0; i < n; i++) {
            int4 r = g_ovf[i];                             // broadcast
            if (r.y == w) {
                float v = __int_as_float(r.z);
                const uint32_t* row = reinterpret_cast<const uint32_t*>(
                    support + (size_t)r.x * OUT_F);
                uint32_t h2raw = __ldg(&row[lane]);
                float2 f = __half22float2(*reinterpret_cast<__half2*>(&h2raw));
                acc.x += v * f.x;
                acc.y += v * f.y;
            }
        }
    }

    float2 b = __ldg(reinterpret_cast<const float2*>(bias) + lane);
    float2 r = make_float2(acc.x + b.x, acc.y + b.y);
    *reinterpret_cast<float2*>(out + (size_t)w * OUT_F + 2 * lane) = r;
}

// ---------------------------------------------------------------------------
extern "C" void kernel_launch(void* const* d_in, const int* in_sizes, int n_in,
                              void* d_out, int out_size) {
    const float* x        = (const float*)d_in[0];
    const float* weight   = (const float*)d_in[1];
    const float* bias     = (const float*)d_in[2];
    const int*   edge_src = (const int*)  d_in[3];
    const int*   edge_dst = (const int*)  d_in[4];
    const float* edge_val = (const float*)d_in[5];
    float* out = (float*)d_out;

    int M  = in_sizes[0] / IN_F;
    int nE = in_sizes[3];

    __half* support; cudaGetSymbolAddress((void**)&support, g_support);

    // 1) GEMM (also zeroes counters for fill/gather)
    gemm_kernel<<<(M + BM - 1) / BM, 256>>>(x, weight, support, M);

    // 2) bucket edges by dst, 4 edges/thread
    {
        int threadsNeeded = (nE + 3) / 4;
        fill_kernel<<<(threadsNeeded + 255) / 256, 256>>>(edge_src, edge_dst, edge_val, nE);
    }

    // 3) per-node gather (+bias, +overflow), one store per node
    gather_kernel<<<(M * 32 + 255) / 256, 256>>>(support, bias, out, M);
}